// round 1
// baseline (speedup 1.0000x reference)
#include <cuda_runtime.h>

// Problem constants
#define DIMK   256        // K of GEMM (h feature dim)
#define NOUT   512        // N of GEMM (2*dim)
#define MROWS  32768      // B*N nodes
#define NEMB   255        // embedding width (dim-1)
#define NEDGE  4194304    // E = 256*128*128

// GEMM tiling
#define BM 128
#define BN 128
#define BKT 16
#define TM 8
#define TN 8

// ---------------------------------------------------------------------------
// Fused h-construction + SGEMM:  out[m][n] = sum_k h[m][k]*W[k][n] + b[n]
// h[m][0] = charges[m]*mask[m]; h[m][1+j] = emb[cat[m]][j]*mask[m]
// ---------------------------------------------------------------------------
__global__ __launch_bounds__(256) void gemm_h_kernel(
    const float* __restrict__ charges,
    const int*   __restrict__ cats,
    const float* __restrict__ nmask,
    const float* __restrict__ emb,    // [100,255] row-major
    const float* __restrict__ W,      // [256,512] row-major
    const float* __restrict__ bias,   // [512]
    float*       __restrict__ out)    // [32768,512]
{
    __shared__ float As[BKT][BM];
    __shared__ float Bs[BKT][BN];
    __shared__ int   s_cat[BM];
    __shared__ float s_chm[BM];   // charge * mask
    __shared__ float s_msk[BM];

    const int bm  = blockIdx.y * BM;
    const int bn  = blockIdx.x * BN;
    const int tid = threadIdx.x;

    if (tid < BM) {
        int r = bm + tid;
        float m = nmask[r];
        s_cat[tid] = cats[r];
        s_msk[tid] = m;
        s_chm[tid] = charges[r] * m;
    }
    __syncthreads();

    float acc[TM][TN];
    #pragma unroll
    for (int i = 0; i < TM; i++)
        #pragma unroll
        for (int j = 0; j < TN; j++) acc[i][j] = 0.f;

    const int ty = tid >> 4;      // 0..15 -> row group
    const int tx = tid & 15;      // 0..15 -> col group

    for (int kb = 0; kb < DIMK; kb += BKT) {
        // ---- load A tile (fused h gather): 128x16 = 2048 elems, 8/thread.
        // e = tid + j*256: consecutive threads hit consecutive k -> coalesced
        // reads within one emb row.
        #pragma unroll
        for (int j = 0; j < 8; j++) {
            int e  = tid + j * 256;
            int kk = e & (BKT - 1);       // 0..15
            int m  = e >> 4;              // 0..127
            int k  = kb + kk;
            float v;
            if (k == 0) v = s_chm[m];
            else        v = __ldg(&emb[s_cat[m] * NEMB + (k - 1)]) * s_msk[m];
            As[kk][m] = v;
        }
        // ---- load B tile: W[kb+k][bn+n], n fastest -> coalesced
        #pragma unroll
        for (int j = 0; j < 8; j++) {
            int e = tid + j * 256;
            int n = e & (BN - 1);
            int k = e >> 7;
            Bs[k][n] = W[(kb + k) * NOUT + bn + n];
        }
        __syncthreads();

        #pragma unroll
        for (int k = 0; k < BKT; k++) {
            float a[TM], b[TN];
            // vectorized smem reads
            *reinterpret_cast<float4*>(&a[0]) = *reinterpret_cast<const float4*>(&As[k][ty * TM]);
            *reinterpret_cast<float4*>(&a[4]) = *reinterpret_cast<const float4*>(&As[k][ty * TM + 4]);
            *reinterpret_cast<float4*>(&b[0]) = *reinterpret_cast<const float4*>(&Bs[k][tx * TN]);
            *reinterpret_cast<float4*>(&b[4]) = *reinterpret_cast<const float4*>(&Bs[k][tx * TN + 4]);
            #pragma unroll
            for (int i = 0; i < TM; i++)
                #pragma unroll
                for (int j = 0; j < TN; j++)
                    acc[i][j] = fmaf(a[i], b[j], acc[i][j]);
        }
        __syncthreads();
    }

    // epilogue: bias add + vectorized store
    #pragma unroll
    for (int i = 0; i < TM; i++) {
        int row = bm + ty * TM + i;
        #pragma unroll
        for (int j = 0; j < TN; j += 4) {
            int col = bn + tx * TN + j;
            float4 v;
            v.x = acc[i][j + 0] + bias[col + 0];
            v.y = acc[i][j + 1] + bias[col + 1];
            v.z = acc[i][j + 2] + bias[col + 2];
            v.w = acc[i][j + 3] + bias[col + 3];
            *reinterpret_cast<float4*>(&out[(size_t)row * NOUT + col]) = v;
        }
    }
}

// ---------------------------------------------------------------------------
// Edge kernel: radial + coord_diff
// ---------------------------------------------------------------------------
__global__ __launch_bounds__(256) void edge_kernel(
    const float* __restrict__ x,      // [32768,3]
    const int*   __restrict__ edges,  // [2, E]
    float*       __restrict__ radial, // [E]
    float*       __restrict__ cd)     // [E,3]
{
    int e = blockIdx.x * 256 + threadIdx.x;
    if (e >= NEDGE) return;
    int r = __ldg(&edges[e]);
    int c = __ldg(&edges[NEDGE + e]);
    float dx = __ldg(&x[3 * r + 0]) - __ldg(&x[3 * c + 0]);
    float dy = __ldg(&x[3 * r + 1]) - __ldg(&x[3 * c + 1]);
    float dz = __ldg(&x[3 * r + 2]) - __ldg(&x[3 * c + 2]);
    float rad = dx * dx + dy * dy + dz * dz;
    float inv = 1.0f / (sqrtf(rad + 1e-8f) + 1.0f);
    radial[e]       = rad;
    cd[3 * e + 0]   = dx * inv;
    cd[3 * e + 1]   = dy * inv;
    cd[3 * e + 2]   = dz * inv;
}

// ---------------------------------------------------------------------------
// Launch
// inputs: 0 x, 1 categories, 2 charges, 3 edges, 4 node_mask, 5 edge_mask,
//         6 emb_table, 7 W, 8 b_lin
// output layout (flat f32): parameters [32768*512] | radial [E] | coord_diff [E*3]
// ---------------------------------------------------------------------------
extern "C" void kernel_launch(void* const* d_in, const int* in_sizes, int n_in,
                              void* d_out, int out_size)
{
    const float* x        = (const float*)d_in[0];
    const int*   cats     = (const int*)  d_in[1];
    const float* charges  = (const float*)d_in[2];
    const int*   edges    = (const int*)  d_in[3];
    const float* nmask    = (const float*)d_in[4];
    // d_in[5] edge_mask unused by the returned outputs
    const float* emb      = (const float*)d_in[6];
    const float* W        = (const float*)d_in[7];
    const float* bias     = (const float*)d_in[8];

    float* out        = (float*)d_out;
    float* out_params = out;                                  // 16,777,216
    float* out_radial = out + (size_t)MROWS * NOUT;           // +4,194,304
    float* out_cd     = out_radial + NEDGE;                   // +12,582,912

    dim3 ggrid(NOUT / BN, MROWS / BM);   // (4, 256)
    gemm_h_kernel<<<ggrid, 256>>>(charges, cats, nmask, emb, W, bias, out_params);

    edge_kernel<<<NEDGE / 256, 256>>>(x, edges, out_radial, out_cd);
}